// round 1
// baseline (speedup 1.0000x reference)
#include <cuda_runtime.h>

// Problem constants
#define NROWS 32768      // B*H*W
#define DDIM  64
#define KCB   1024
#define MT    128        // rows per CTA
#define NT    128        // codebook entries per k-tile
#define NKT   (KCB / NT) // 8 k-tiles
#define NTHREADS 256

// Output layout (float32, concatenated in reference return order)
#define OFF_ZQ    0
#define OFF_LOSS  2097152
#define OFF_PERP  2097153
#define OFF_IDX   2097154
#define OFF_DIST  2129922
// total = 35684354

// Scratch (allocation-free rule: device globals)
__device__ float        g_loss;
__device__ unsigned int g_counts[KCB];

__global__ void vq_init_kernel() {
    int t = threadIdx.x;
    if (t < KCB) g_counts[t] = 0u;
    if (t == 0) g_loss = 0.0f;
}

// smem layout (floats):
//   f_s  [64][128]  : 8192   (f tile, d-major)
//   e_s  [64][128]  : 8192   (e tile, d-major)
//   f2_s [128]      : 128
//   e2_s [128]      : 128
//   idx_s[128] (int): 128
//   red  [256]      : 256
// total 17024 floats = 68096 bytes
#define SMEM_FLOATS 17024

__global__ void __launch_bounds__(NTHREADS, 2)
vq_main_kernel(const float* __restrict__ z_e,
               const float* __restrict__ emb,
               float* __restrict__ zq_out,
               float* __restrict__ idx_out,
               float* __restrict__ dist_out)
{
    extern __shared__ float smem[];
    float* f_s  = smem;                 // [64][128]
    float* e_s  = smem + 8192;          // [64][128]
    float* f2_s = smem + 16384;         // [128]
    float* e2_s = f2_s + 128;           // [128]
    int*   idx_s = (int*)(e2_s + 128);  // [128]
    float* red  = (float*)(idx_s + 128);// [256]

    const int t  = threadIdx.x;
    const int tx = t & 15;              // k direction (16)
    const int ty = t >> 4;              // m direction (16)

    const int n0  = blockIdx.x * MT;    // first row of this CTA
    const int b   = n0 >> 10;           // batch (1024 rows per batch)
    const int hw0 = n0 & 1023;          // h*W + w offset within batch

    const float* zbase = z_e + (size_t)b * (DDIM * 1024) + hw0;

    // ---- load f tile: f_s[d][m] = z_e[b, d, hw0+m] (coalesced float4) ----
    #pragma unroll
    for (int it = 0; it < 8; ++it) {
        int li = it * NTHREADS + t;     // 0..2047
        int d  = li >> 5;               // 0..63
        int m4 = li & 31;               // float4 index along m
        float4 v = *(const float4*)(zbase + (size_t)d * 1024 + m4 * 4);
        *(float4*)(f_s + d * 128 + m4 * 4) = v;
    }
    __syncthreads();

    // ---- f2 per row ----
    if (t < 128) {
        float s = 0.0f;
        #pragma unroll
        for (int d = 0; d < DDIM; ++d) {
            float v = f_s[d * 128 + t];
            s = fmaf(v, v, s);
        }
        f2_s[t] = s;
    }

    // ---- running argmin state (8 rows per thread) ----
    float bestv[8];
    int   besti[8];
    #pragma unroll
    for (int i = 0; i < 8; ++i) { bestv[i] = 3.0e38f; besti[i] = 0; }

    // ---- loop over the 8 codebook tiles ----
    #pragma unroll 1
    for (int kt = 0; kt < NKT; ++kt) {
        const int k0 = kt * NT;
        __syncthreads();  // protect e_s / e2_s reuse

        // load e tile: e_s[d][kk] = emb[k0+kk][d]
        #pragma unroll
        for (int it = 0; it < 8; ++it) {
            int li = it * NTHREADS + t;   // 0..2047
            int kk = li & 127;
            int dc = li >> 7;             // 0..15 float4-chunk along d
            float4 v = *(const float4*)(emb + (size_t)(k0 + kk) * DDIM + dc * 4);
            e_s[(dc * 4 + 0) * 128 + kk] = v.x;
            e_s[(dc * 4 + 1) * 128 + kk] = v.y;
            e_s[(dc * 4 + 2) * 128 + kk] = v.z;
            e_s[(dc * 4 + 3) * 128 + kk] = v.w;
        }
        __syncthreads();

        if (t < 128) {
            float s = 0.0f;
            #pragma unroll
            for (int d = 0; d < DDIM; ++d) {
                float v = e_s[d * 128 + t];
                s = fmaf(v, v, s);
            }
            e2_s[t] = s;
        }
        __syncthreads();

        // 8x8 register microtile GEMM over d
        float acc[8][8];
        #pragma unroll
        for (int i = 0; i < 8; ++i)
            #pragma unroll
            for (int j = 0; j < 8; ++j)
                acc[i][j] = 0.0f;

        #pragma unroll 4
        for (int d = 0; d < DDIM; ++d) {
            float4 fa = *(float4*)(f_s + d * 128 + ty * 8);
            float4 fb = *(float4*)(f_s + d * 128 + ty * 8 + 4);
            float4 ea = *(float4*)(e_s + d * 128 + tx * 8);
            float4 eb = *(float4*)(e_s + d * 128 + tx * 8 + 4);
            float fr[8] = {fa.x, fa.y, fa.z, fa.w, fb.x, fb.y, fb.z, fb.w};
            float er[8] = {ea.x, ea.y, ea.z, ea.w, eb.x, eb.y, eb.z, eb.w};
            #pragma unroll
            for (int i = 0; i < 8; ++i)
                #pragma unroll
                for (int j = 0; j < 8; ++j)
                    acc[i][j] = fmaf(fr[i], er[j], acc[i][j]);
        }

        // epilogue: distances + argmin update + store
        #pragma unroll
        for (int i = 0; i < 8; ++i) {
            const int m  = ty * 8 + i;
            const float f2 = f2_s[m];
            float w[8];
            #pragma unroll
            for (int j = 0; j < 8; ++j) {
                const int k = k0 + tx * 8 + j;
                float v = fmaf(-2.0f, acc[i][j], f2 + e2_s[tx * 8 + j]);
                w[j] = v;
                if (v < bestv[i]) { bestv[i] = v; besti[i] = k; }
            }
            // dist segment is only 8B-aligned in the output buffer -> float2 stores
            float* drow = dist_out + (size_t)(n0 + m) * KCB + k0 + tx * 8;
            *(float2*)(drow + 0) = make_float2(w[0], w[1]);
            *(float2*)(drow + 2) = make_float2(w[2], w[3]);
            *(float2*)(drow + 4) = make_float2(w[4], w[5]);
            *(float2*)(drow + 6) = make_float2(w[6], w[7]);
        }
    }

    // ---- argmin reduction across the 16 tx lanes (shfl width 16) ----
    const unsigned mask = 0xffffffffu;
    #pragma unroll
    for (int i = 0; i < 8; ++i) {
        float v  = bestv[i];
        int   bi = besti[i];
        #pragma unroll
        for (int off = 8; off > 0; off >>= 1) {
            float ov = __shfl_down_sync(mask, v,  off, 16);
            int   oi = __shfl_down_sync(mask, bi, off, 16);
            if (ov < v || (ov == v && oi < bi)) { v = ov; bi = oi; }
        }
        if (tx == 0) idx_s[ty * 8 + i] = bi;
    }
    __syncthreads();

    // ---- index output + histogram ----
    if (t < 128) {
        int bi = idx_s[t];
        idx_out[n0 + t] = (float)bi;
        atomicAdd(&g_counts[bi], 1u);
    }

    // ---- z_q gather/scatter + loss partial ----
    float lsum = 0.0f;
    float* zq_base = zq_out + (size_t)b * (DDIM * 1024) + hw0;
    #pragma unroll 4
    for (int it = 0; it < 32; ++it) {
        int li = it * NTHREADS + t;  // 0..8191
        int d  = li >> 7;            // 0..63
        int m  = li & 127;
        float v  = emb[(size_t)idx_s[m] * DDIM + d];
        float fv = f_s[d * 128 + m];
        float df = v - fv;
        lsum = fmaf(df, df, lsum);
        zq_base[(size_t)d * 1024 + m] = v;
    }
    red[t] = lsum;
    __syncthreads();
    #pragma unroll
    for (int s = 128; s > 0; s >>= 1) {
        if (t < s) red[t] += red[t + s];
        __syncthreads();
    }
    if (t == 0) atomicAdd(&g_loss, red[0]);
}

__global__ void vq_finalize_kernel(float* __restrict__ loss_out,
                                   float* __restrict__ perp_out)
{
    __shared__ float red[KCB];
    int t = threadIdx.x;
    float c = (float)g_counts[t];
    float p = c * (1.0f / (float)NROWS);
    red[t] = p * logf(p + 1e-10f);
    __syncthreads();
    #pragma unroll
    for (int s = KCB / 2; s > 0; s >>= 1) {
        if (t < s) red[t] += red[t + s];
        __syncthreads();
    }
    if (t == 0) {
        *perp_out = expf(-red[0]);
        // codebook_loss == commitment_loss in value -> 1.25 * MSE
        *loss_out = g_loss * (1.25f / (float)(NROWS * DDIM));
    }
}

extern "C" void kernel_launch(void* const* d_in, const int* in_sizes, int n_in,
                              void* d_out, int out_size)
{
    const float* z_e = (const float*)d_in[0];
    const float* emb = (const float*)d_in[1];
    float* out = (float*)d_out;

    float* zq   = out + OFF_ZQ;
    float* loss = out + OFF_LOSS;
    float* perp = out + OFF_PERP;
    float* idxf = out + OFF_IDX;
    float* dist = out + OFF_DIST;

    // idempotent, not an allocation; safe to call every launch
    cudaFuncSetAttribute(vq_main_kernel,
                         cudaFuncAttributeMaxDynamicSharedMemorySize,
                         SMEM_FLOATS * sizeof(float));

    vq_init_kernel<<<1, 1024>>>();
    vq_main_kernel<<<NROWS / MT, NTHREADS, SMEM_FLOATS * sizeof(float)>>>(
        z_e, emb, zq, idxf, dist);
    vq_finalize_kernel<<<1, KCB>>>(loss, perp);
}